// round 1
// baseline (speedup 1.0000x reference)
#include <cuda_runtime.h>
#include <cuda_bf16.h>

#define NB 8
#define CH 64
#define HH 256
#define WW 256
#define PP (HH*WW)   // 65536 pixels per batch

// Scratch: NHWC-transposed feature and NHWC intermediate (128 MB each).
__device__ float g_fN[(size_t)NB * PP * CH];
__device__ float g_first[(size_t)NB * PP * CH];

// ---------------------------------------------------------------------------
// K1: NCHW -> NHWC transpose, per batch: [64][65536] -> [65536][64]
// 32x32 smem tile, fully coalesced both directions.
// ---------------------------------------------------------------------------
__global__ void k_transpose(const float* __restrict__ feat) {
    __shared__ float sm[32][33];
    const int n     = blockIdx.z;
    const int cbase = blockIdx.y * 32;   // 0 or 32
    const int pbase = blockIdx.x * 32;   // pixel tile
    const int tx = threadIdx.x, ty = threadIdx.y;

    const float* src = feat + (size_t)n * CH * PP;
    #pragma unroll
    for (int i = 0; i < 4; i++) {
        int c = cbase + ty + i * 8;
        sm[ty + i * 8][tx] = src[(size_t)c * PP + pbase + tx];
    }
    __syncthreads();
    float* dst = g_fN + (size_t)n * PP * CH;
    #pragma unroll
    for (int i = 0; i < 4; i++) {
        int prow = ty + i * 8;
        dst[(size_t)(pbase + prow) * CH + cbase + tx] = sm[tx][prow];
    }
}

// ---------------------------------------------------------------------------
// Bilinear helpers (match reference math exactly, fp32, zeros padding)
// ---------------------------------------------------------------------------
__device__ __forceinline__ void bl_setup(float gx, float gy,
                                         int& x0, int& y0, float& fx, float& fy) {
    float ix = ((gx + 1.0f) * (float)WW - 1.0f) * 0.5f;
    float iy = ((gy + 1.0f) * (float)HH - 1.0f) * 0.5f;
    float fx0 = floorf(ix);
    float fy0 = floorf(iy);
    fx = ix - fx0;
    fy = iy - fy0;
    x0 = (int)fx0;
    y0 = (int)fy0;
}

// src = NHWC slice for batch n ([256][256][64]); returns sample for channel c.
__device__ __forceinline__ float bl_sample(const float* __restrict__ src,
                                           int x0, int y0, float fx, float fy, int c) {
    const int x1 = x0 + 1, y1 = y0 + 1;
    const bool vx0 = (x0 >= 0) & (x0 < WW);
    const bool vx1 = (x1 >= 0) & (x1 < WW);
    const bool vy0 = (y0 >= 0) & (y0 < HH);
    const bool vy1 = (y1 >= 0) & (y1 < HH);

    float v00 = (vx0 & vy0) ? src[(((y0 << 8) + x0) << 6) + c] : 0.0f;
    float v01 = (vx1 & vy0) ? src[(((y0 << 8) + x1) << 6) + c] : 0.0f;
    float v10 = (vx0 & vy1) ? src[(((y1 << 8) + x0) << 6) + c] : 0.0f;
    float v11 = (vx1 & vy1) ? src[(((y1 << 8) + x1) << 6) + c] : 0.0f;

    const float wx1 = fx, wy1 = fy;
    const float wx0 = 1.0f - fx, wy0 = 1.0f - fy;
    return v00 * (wx0 * wy0) + v01 * (wx1 * wy0)
         + v10 * (wx0 * wy1) + v11 * (wx1 * wy1);
}

// ---------------------------------------------------------------------------
// K2: pass 1. 256 threads = 4 pixels x 64 channels. Lane group shares one
// pixel's grid coords; each corner gather is a contiguous 256B warp load.
// Writes intermediate in NHWC (coalesced).
// ---------------------------------------------------------------------------
__global__ void k_pass1(const float* __restrict__ grid) {
    const int tid  = threadIdx.x;
    const int c    = tid & 63;
    const int pixg = blockIdx.x * 4 + (tid >> 6);   // global pixel id over N*P
    const int n    = pixg >> 16;
    const int p    = pixg & (PP - 1);

    const float2 g = ((const float2*)grid)[(size_t)n * PP + p];
    int x0, y0; float fx, fy;
    bl_setup(g.x, g.y, x0, y0, fx, fy);

    const float* src = g_fN + (size_t)n * PP * CH;
    float r = bl_sample(src, x0, y0, fx, fy, c);
    g_first[((size_t)n * PP + p) * CH + c] = r;
}

// ---------------------------------------------------------------------------
// K3: pass 2. Block handles 32 consecutive output pixels x 64 channels.
// Phase A: NHWC gathers into smem tile [c][pixel].
// Phase B: coalesced NCHW output writes (128B contiguous per channel row).
// ---------------------------------------------------------------------------
__global__ void k_pass2(const float* __restrict__ grid, float* __restrict__ out) {
    __shared__ float sm[64][33];
    const int n    = blockIdx.x >> 11;            // / 2048
    const int p0   = (blockIdx.x & 2047) * 32;    // 32-pixel aligned run
    const int tid  = threadIdx.x;
    const int c    = tid & 63;
    const int psub = tid >> 6;                    // 0..3

    const float* src = g_first + (size_t)n * PP * CH;
    #pragma unroll
    for (int i = 0; i < 8; i++) {
        const int pl = i * 4 + psub;
        const int p  = p0 + pl;
        const float2 g = ((const float2*)grid)[(size_t)n * PP + p];
        int x0, y0; float fx, fy;
        bl_setup(g.x, g.y, x0, y0, fx, fy);
        sm[c][pl] = bl_sample(src, x0, y0, fx, fy, c);
    }
    __syncthreads();

    const int w = tid >> 5, lane = tid & 31;
    #pragma unroll
    for (int j = 0; j < 8; j++) {
        const int cc = w * 8 + j;
        out[(((size_t)n * CH + cc) << 16) + p0 + lane] = sm[cc][lane];
    }
}

// ---------------------------------------------------------------------------
extern "C" void kernel_launch(void* const* d_in, const int* in_sizes, int n_in,
                              void* d_out, int out_size) {
    const float* feature = (const float*)d_in[0];
    const float* grid    = (const float*)d_in[1];
    float*       out     = (float*)d_out;

    // K1: transpose NCHW -> NHWC
    k_transpose<<<dim3(PP / 32, CH / 32, NB), dim3(32, 8)>>>(feature);

    // K2: first grid_sample (NHWC -> NHWC intermediate)
    k_pass1<<<(NB * PP) / 4, 256>>>(grid);

    // K3: second grid_sample (NHWC -> NCHW output via smem staging)
    k_pass2<<<(NB * PP) / 32, 256>>>(grid, out);
}

// round 3
// speedup vs baseline: 1.5168x; 1.5168x over previous
#include <cuda_runtime.h>
#include <cuda_bf16.h>

#define NB 8
#define CH 64
#define HH 256
#define WW 256
#define PP (HH*WW)   // 65536 pixels per batch

// Per-batch scratch, reused across batches so it stays L2-resident (16MB each).
__device__ float g_fN[(size_t)PP * CH];     // NHWC feature slice for current batch
__device__ float g_first[(size_t)PP * CH];  // NHWC intermediate for current batch

// ---------------------------------------------------------------------------
// K1: NCHW -> NHWC transpose for one batch: [64][65536] -> [65536][64]
// ---------------------------------------------------------------------------
__global__ void k_transpose(const float* __restrict__ feat, int n) {
    __shared__ float sm[32][33];
    const int cbase = blockIdx.y * 32;   // 0 or 32
    const int pbase = blockIdx.x * 32;   // pixel tile
    const int tx = threadIdx.x, ty = threadIdx.y;

    const float* src = feat + (size_t)n * CH * PP;
    #pragma unroll
    for (int i = 0; i < 4; i++) {
        int c = cbase + ty + i * 8;
        sm[ty + i * 8][tx] = src[(size_t)c * PP + pbase + tx];
    }
    __syncthreads();
    #pragma unroll
    for (int i = 0; i < 4; i++) {
        int prow = ty + i * 8;
        g_fN[(size_t)(pbase + prow) * CH + cbase + tx] = sm[tx][prow];
    }
}

// ---------------------------------------------------------------------------
// Bilinear helpers (match reference math, fp32, zeros padding)
// ---------------------------------------------------------------------------
__device__ __forceinline__ void bl_setup(float gx, float gy,
                                         int& x0, int& y0, float& fx, float& fy) {
    float ix = ((gx + 1.0f) * (float)WW - 1.0f) * 0.5f;
    float iy = ((gy + 1.0f) * (float)HH - 1.0f) * 0.5f;
    float fx0 = floorf(ix);
    float fy0 = floorf(iy);
    fx = ix - fx0;
    fy = iy - fy0;
    x0 = (int)fx0;
    y0 = (int)fy0;
}

__device__ __forceinline__ float4 f4zero() { return make_float4(0.f, 0.f, 0.f, 0.f); }

__device__ __forceinline__ float4 f4fma(float4 a, float w, float4 acc) {
    acc.x += a.x * w; acc.y += a.y * w; acc.z += a.z * w; acc.w += a.w * w;
    return acc;
}

// src viewed as [PP][16] float4; returns bilinear sample for float4-chunk c4.
__device__ __forceinline__ float4 bl_sample4(const float4* __restrict__ src,
                                             int x0, int y0, float fx, float fy, int c4) {
    const int x1 = x0 + 1, y1 = y0 + 1;
    const bool vx0 = (x0 >= 0) & (x0 < WW);
    const bool vx1 = (x1 >= 0) & (x1 < WW);
    const bool vy0 = (y0 >= 0) & (y0 < HH);
    const bool vy1 = (y1 >= 0) & (y1 < HH);

    float4 v00 = (vx0 & vy0) ? src[(((y0 << 8) + x0) << 4) + c4] : f4zero();
    float4 v01 = (vx1 & vy0) ? src[(((y0 << 8) + x1) << 4) + c4] : f4zero();
    float4 v10 = (vx0 & vy1) ? src[(((y1 << 8) + x0) << 4) + c4] : f4zero();
    float4 v11 = (vx1 & vy1) ? src[(((y1 << 8) + x1) << 4) + c4] : f4zero();

    const float wx1 = fx, wy1 = fy;
    const float wx0 = 1.0f - fx, wy0 = 1.0f - fy;
    float4 r = f4zero();
    r = f4fma(v00, wx0 * wy0, r);
    r = f4fma(v01, wx1 * wy0, r);
    r = f4fma(v10, wx0 * wy1, r);
    r = f4fma(v11, wx1 * wy1, r);
    return r;
}

// ---------------------------------------------------------------------------
// K2: pass 1 for one batch. 256 threads = 16 pixels x 16 float4-chunks.
// NHWC gather from g_fN (L2-resident), coalesced NHWC write to g_first.
// ---------------------------------------------------------------------------
__global__ void k_pass1(const float* __restrict__ grid, int n) {
    const int tid = threadIdx.x;
    const int c4  = tid & 15;
    const int p   = blockIdx.x * 16 + (tid >> 4);

    const float2 g = ((const float2*)grid)[(size_t)n * PP + p];
    int x0, y0; float fx, fy;
    bl_setup(g.x, g.y, x0, y0, fx, fy);

    float4 r = bl_sample4((const float4*)g_fN, x0, y0, fx, fy, c4);
    ((float4*)g_first)[(size_t)p * 16 + c4] = r;
}

// ---------------------------------------------------------------------------
// K3: pass 2 for one batch. 512 threads = 32 pixels x 16 float4-chunks.
// NHWC gather from g_first (L2-resident), smem-staged NCHW output write.
// ---------------------------------------------------------------------------
__global__ void k_pass2(const float* __restrict__ grid, float* __restrict__ out, int n) {
    __shared__ float sm[64][33];
    const int tid  = threadIdx.x;
    const int c4   = tid & 15;
    const int pl   = tid >> 4;                 // 0..31
    const int p0   = blockIdx.x * 32;
    const int p    = p0 + pl;

    const float2 g = ((const float2*)grid)[(size_t)n * PP + p];
    int x0, y0; float fx, fy;
    bl_setup(g.x, g.y, x0, y0, fx, fy);

    float4 r = bl_sample4((const float4*)g_first, x0, y0, fx, fy, c4);
    const int cb = c4 * 4;
    sm[cb + 0][pl] = r.x;
    sm[cb + 1][pl] = r.y;
    sm[cb + 2][pl] = r.z;
    sm[cb + 3][pl] = r.w;
    __syncthreads();

    const int w = tid >> 5, lane = tid & 31;   // 16 warps
    #pragma unroll
    for (int k = 0; k < 4; k++) {
        const int cc = w * 4 + k;
        out[(((size_t)n * CH + cc) << 16) + p0 + lane] = sm[cc][lane];
    }
}

// ---------------------------------------------------------------------------
extern "C" void kernel_launch(void* const* d_in, const int* in_sizes, int n_in,
                              void* d_out, int out_size) {
    const float* feature = (const float*)d_in[0];
    const float* grid    = (const float*)d_in[1];
    float*       out     = (float*)d_out;

    for (int n = 0; n < NB; n++) {
        k_transpose<<<dim3(PP / 32, CH / 32), dim3(32, 8)>>>(feature, n);
        k_pass1<<<PP / 16, 256>>>(grid, n);
        k_pass2<<<PP / 32, 512>>>(grid, out, n);
    }
}

// round 4
// speedup vs baseline: 1.6933x; 1.1164x over previous
#include <cuda_runtime.h>
#include <cuda_bf16.h>

#define NB 8
#define CH 64
#define HH 256
#define WW 256
#define PP (HH*WW)   // 65536 pixels per batch

// Double-buffered NHWC feature slice (2x16MB) + NHWC intermediate (16MB).
// All reused across batches -> stays L2-resident (~48MB << 126MB L2).
__device__ float g_fN[2][(size_t)PP * CH];
__device__ float g_first[(size_t)PP * CH];

// ---------------------------------------------------------------------------
// Transpose one 64ch x 64px tile of batch n (NCHW -> NHWC) into g_fN[buf].
// 256 threads. float4 global loads (4 indep 16B loads/thread), coalesced
// 128B NHWC stores.
// ---------------------------------------------------------------------------
__device__ __forceinline__ void transpose_tile(const float* __restrict__ feat,
                                               int n, int buf, int tile,
                                               float* __restrict__ sm /*64*65*/) {
    const int pbase = tile * 64;
    const int t = threadIdx.x;
    const float* src = feat + (size_t)n * CH * PP;

    const int px4 = (t & 15) * 4;   // pixel offset 0..60
    const int c0  = t >> 4;         // 0..15
    #pragma unroll
    for (int i = 0; i < 4; i++) {
        const int c = c0 + i * 16;
        const float4 v = *(const float4*)(src + (size_t)c * PP + pbase + px4);
        sm[c * 65 + px4 + 0] = v.x;
        sm[c * 65 + px4 + 1] = v.y;
        sm[c * 65 + px4 + 2] = v.z;
        sm[c * 65 + px4 + 3] = v.w;
    }
    __syncthreads();

    float* dst = g_fN[buf];
    const int c   = t & 63;
    const int pxb = t >> 6;         // 0..3
    #pragma unroll
    for (int i = 0; i < 16; i++) {
        const int px = pxb + i * 4;
        dst[(size_t)(pbase + px) * 64 + c] = sm[c * 65 + px];
    }
}

// ---------------------------------------------------------------------------
// Bilinear helpers (match reference math, fp32, zeros padding)
// ---------------------------------------------------------------------------
__device__ __forceinline__ void bl_setup(float gx, float gy,
                                         int& x0, int& y0, float& fx, float& fy) {
    float ix = ((gx + 1.0f) * (float)WW - 1.0f) * 0.5f;
    float iy = ((gy + 1.0f) * (float)HH - 1.0f) * 0.5f;
    float fx0 = floorf(ix);
    float fy0 = floorf(iy);
    fx = ix - fx0;
    fy = iy - fy0;
    x0 = (int)fx0;
    y0 = (int)fy0;
}

__device__ __forceinline__ float4 f4zero() { return make_float4(0.f, 0.f, 0.f, 0.f); }

__device__ __forceinline__ float4 f4fma(float4 a, float w, float4 acc) {
    acc.x += a.x * w; acc.y += a.y * w; acc.z += a.z * w; acc.w += a.w * w;
    return acc;
}

// src viewed as [PP][16] float4; bilinear sample for float4-chunk c4.
__device__ __forceinline__ float4 bl_sample4(const float4* __restrict__ src,
                                             int x0, int y0, float fx, float fy, int c4) {
    const int x1 = x0 + 1, y1 = y0 + 1;
    const bool vx0 = (x0 >= 0) & (x0 < WW);
    const bool vx1 = (x1 >= 0) & (x1 < WW);
    const bool vy0 = (y0 >= 0) & (y0 < HH);
    const bool vy1 = (y1 >= 0) & (y1 < HH);

    float4 v00 = (vx0 & vy0) ? src[(((y0 << 8) + x0) << 4) + c4] : f4zero();
    float4 v01 = (vx1 & vy0) ? src[(((y0 << 8) + x1) << 4) + c4] : f4zero();
    float4 v10 = (vx0 & vy1) ? src[(((y1 << 8) + x0) << 4) + c4] : f4zero();
    float4 v11 = (vx1 & vy1) ? src[(((y1 << 8) + x1) << 4) + c4] : f4zero();

    const float wx1 = fx, wy1 = fy;
    const float wx0 = 1.0f - fx, wy0 = 1.0f - fy;
    float4 r = f4zero();
    r = f4fma(v00, wx0 * wy0, r);
    r = f4fma(v01, wx1 * wy0, r);
    r = f4fma(v10, wx0 * wy1, r);
    r = f4fma(v11, wx1 * wy1, r);
    return r;
}

// ---------------------------------------------------------------------------
// Pass1 block: 16 pixels x 16 float4-chunks = 256 threads.
// ---------------------------------------------------------------------------
__device__ __forceinline__ void pass1_block(const float* __restrict__ grid,
                                            int n, int buf, int blk) {
    const int t  = threadIdx.x;
    const int c4 = t & 15;
    const int p  = blk * 16 + (t >> 4);

    const float2 g = ((const float2*)grid)[(size_t)n * PP + p];
    int x0, y0; float fx, fy;
    bl_setup(g.x, g.y, x0, y0, fx, fy);

    float4 r = bl_sample4((const float4*)g_fN[buf], x0, y0, fx, fy, c4);
    ((float4*)g_first)[(size_t)p * 16 + c4] = r;
}

// ---------------------------------------------------------------------------
// Pass2 block: 32 pixels x 64 channels with 256 threads; smem-staged NCHW out.
// sm2 is 64*33 floats.
// ---------------------------------------------------------------------------
__device__ __forceinline__ void pass2_block(const float* __restrict__ grid,
                                            float* __restrict__ out,
                                            int n, int blk,
                                            float* __restrict__ sm2) {
    const int t   = threadIdx.x;
    const int c4  = t & 15;
    const int pl0 = t >> 4;           // 0..15
    const int p0  = blk * 32;

    #pragma unroll
    for (int i = 0; i < 2; i++) {
        const int pl = pl0 + 16 * i;
        const int p  = p0 + pl;
        const float2 g = ((const float2*)grid)[(size_t)n * PP + p];
        int x0, y0; float fx, fy;
        bl_setup(g.x, g.y, x0, y0, fx, fy);
        float4 r = bl_sample4((const float4*)g_first, x0, y0, fx, fy, c4);
        const int cb = c4 * 4;
        sm2[(cb + 0) * 33 + pl] = r.x;
        sm2[(cb + 1) * 33 + pl] = r.y;
        sm2[(cb + 2) * 33 + pl] = r.z;
        sm2[(cb + 3) * 33 + pl] = r.w;
    }
    __syncthreads();

    const int w = t >> 5, lane = t & 31;     // 8 warps
    #pragma unroll
    for (int k = 0; k < 8; k++) {
        const int cc = w + 8 * k;
        out[(((size_t)n * CH + cc) << 16) + p0 + lane] = sm2[cc * 33 + lane];
    }
}

// ---------------------------------------------------------------------------
// Prologue: full transpose of batch 0 (1024 tiles).
// ---------------------------------------------------------------------------
__global__ void k_transpose0(const float* __restrict__ feat) {
    __shared__ float sm[64 * 65];
    transpose_tile(feat, 0, 0, blockIdx.x, sm);
}

// Fused kernel A(n): blocks [0,512) = transpose tiles 0..511 of batch n+1;
// blocks [512, 512+4096) = pass1(n).
__global__ void k_fusedA(const float* __restrict__ feat,
                         const float* __restrict__ grid, int n) {
    __shared__ float sm[64 * 65];
    if (blockIdx.x < 512) {
        if (n + 1 < NB)
            transpose_tile(feat, n + 1, (n + 1) & 1, blockIdx.x, sm);
    } else {
        pass1_block(grid, n, n & 1, blockIdx.x - 512);
    }
}

// Fused kernel B(n): blocks [0,512) = transpose tiles 512..1023 of batch n+1;
// blocks [512, 512+2048) = pass2(n).
__global__ void k_fusedB(const float* __restrict__ feat,
                         const float* __restrict__ grid,
                         float* __restrict__ out, int n) {
    __shared__ float sm[64 * 65];
    if (blockIdx.x < 512) {
        if (n + 1 < NB)
            transpose_tile(feat, n + 1, (n + 1) & 1, 512 + blockIdx.x, sm);
    } else {
        pass2_block(grid, out, n, blockIdx.x - 512, sm);
    }
}

// ---------------------------------------------------------------------------
extern "C" void kernel_launch(void* const* d_in, const int* in_sizes, int n_in,
                              void* d_out, int out_size) {
    const float* feature = (const float*)d_in[0];
    const float* grid    = (const float*)d_in[1];
    float*       out     = (float*)d_out;

    k_transpose0<<<PP / 64, 256>>>(feature);
    for (int n = 0; n < NB; n++) {
        k_fusedA<<<512 + PP / 16, 256>>>(feature, grid, n);
        k_fusedB<<<512 + PP / 32, 256>>>(feature, grid, out, n);
    }
}

// round 6
// speedup vs baseline: 2.0226x; 1.1945x over previous
#include <cuda_runtime.h>
#include <cuda_fp16.h>

#define NB 8
#define CH 64
#define HH 256
#define WW 256
#define PP (HH*WW)   // 65536 pixels per batch

// fp16 scratch: double-buffered NHWC feature (2x8MB) + NHWC intermediate (8MB).
// 24MB total -> comfortably L2-resident (126MB L2).
__device__ __half g_fN[2][(size_t)PP * CH];
__device__ __half g_first[(size_t)PP * CH];

// ---------------------------------------------------------------------------
// Transpose one 64ch x 64px tile of batch n: fp32 NCHW -> fp16 NHWC.
// 256 threads; float4 global loads, 128B-per-row uint4 fp16 stores.
// ---------------------------------------------------------------------------
__device__ __forceinline__ void transpose_tile(const float* __restrict__ feat,
                                               int n, int buf, int tile,
                                               float* __restrict__ sm /*64*65*/) {
    const int pbase = tile * 64;
    const int t = threadIdx.x;
    const float* src = feat + (size_t)n * CH * PP;

    const int px4 = (t & 15) * 4;   // pixel offset 0..60
    const int c0  = t >> 4;         // 0..15
    #pragma unroll
    for (int i = 0; i < 4; i++) {
        const int c = c0 + i * 16;
        const float4 v = *(const float4*)(src + (size_t)c * PP + pbase + px4);
        sm[c * 65 + px4 + 0] = v.x;
        sm[c * 65 + px4 + 1] = v.y;
        sm[c * 65 + px4 + 2] = v.z;
        sm[c * 65 + px4 + 3] = v.w;
    }
    __syncthreads();

    __half* dst = g_fN[buf];
    const int c8  = t & 7;          // 8-channel chunk
    const int px0 = t >> 3;         // 0..31
    #pragma unroll
    for (int i = 0; i < 2; i++) {
        const int px = px0 + 32 * i;
        __half2 h[4];
        #pragma unroll
        for (int k = 0; k < 4; k++) {
            float2 f = make_float2(sm[(c8 * 8 + 2 * k) * 65 + px],
                                   sm[(c8 * 8 + 2 * k + 1) * 65 + px]);
            h[k] = __float22half2_rn(f);
        }
        ((uint4*)(dst + (size_t)(pbase + px) * 64))[c8] = *(uint4*)h;
    }
    __syncthreads();
}

// ---------------------------------------------------------------------------
// Bilinear helpers (fp32 math, zeros padding; fp16 storage)
// ---------------------------------------------------------------------------
__device__ __forceinline__ void bl_setup(float gx, float gy,
                                         int& x0, int& y0, float& fx, float& fy) {
    float ix = ((gx + 1.0f) * (float)WW - 1.0f) * 0.5f;
    float iy = ((gy + 1.0f) * (float)HH - 1.0f) * 0.5f;
    float fx0 = floorf(ix);
    float fy0 = floorf(iy);
    fx = ix - fx0;
    fy = iy - fy0;
    x0 = (int)fx0;
    y0 = (int)fy0;
}

// Load the 4 corner uint4s (8 fp16 channels each) for one pixel.
__device__ __forceinline__ void load4(const uint4* __restrict__ src,
                                      int x0, int y0, int c8, uint4* v) {
    const int x1 = x0 + 1, y1 = y0 + 1;
    const bool vx0 = (x0 >= 0) & (x0 < WW);
    const bool vx1 = (x1 >= 0) & (x1 < WW);
    const bool vy0 = (y0 >= 0) & (y0 < HH);
    const bool vy1 = (y1 >= 0) & (y1 < HH);
    const uint4 z = make_uint4(0, 0, 0, 0);
    v[0] = (vx0 & vy0) ? src[(((y0 << 8) + x0) << 3) + c8] : z;
    v[1] = (vx1 & vy0) ? src[(((y0 << 8) + x1) << 3) + c8] : z;
    v[2] = (vx0 & vy1) ? src[(((y1 << 8) + x0) << 3) + c8] : z;
    v[3] = (vx1 & vy1) ? src[(((y1 << 8) + x1) << 3) + c8] : z;
}

// Weighted accumulate of 4 corner uint4s into 8 fp32 channel values.
__device__ __forceinline__ void accum(const uint4* v, float fx, float fy,
                                      float* acc) {
    const float wx1 = fx, wy1 = fy, wx0 = 1.0f - fx, wy0 = 1.0f - fy;
    const float w[4] = {wx0 * wy0, wx1 * wy0, wx0 * wy1, wx1 * wy1};
    #pragma unroll
    for (int j = 0; j < 4; j++) {
        const __half2* h = (const __half2*)&v[j];
        #pragma unroll
        for (int k = 0; k < 4; k++) {
            float2 f = __half22float2(h[k]);
            acc[2 * k]     += f.x * w[j];
            acc[2 * k + 1] += f.y * w[j];
        }
    }
}

__device__ __forceinline__ void store_h8(__half* __restrict__ dst, int p, int c8,
                                         const float* acc) {
    __half2 h[4];
    #pragma unroll
    for (int k = 0; k < 4; k++)
        h[k] = __float22half2_rn(make_float2(acc[2 * k], acc[2 * k + 1]));
    ((uint4*)(dst + (size_t)p * 64))[c8] = *(uint4*)h;
}

// ---------------------------------------------------------------------------
// Pass1 block: 64 pixels x 64 channels, 256 threads, 2 pixels/thread.
// 8 independent 16B corner gathers in flight per thread.
// ---------------------------------------------------------------------------
__device__ __forceinline__ void pass1_block(const float* __restrict__ grid,
                                            int n, int buf, int blk) {
    const int t  = threadIdx.x;
    const int c8 = t & 7;
    const int px = t >> 3;
    const int pA = blk * 64 + px;
    const int pB = pA + 32;

    const float2 gA = ((const float2*)grid)[(size_t)n * PP + pA];
    const float2 gB = ((const float2*)grid)[(size_t)n * PP + pB];
    int xA, yA, xB, yB; float fxA, fyA, fxB, fyB;
    bl_setup(gA.x, gA.y, xA, yA, fxA, fyA);
    bl_setup(gB.x, gB.y, xB, yB, fxB, fyB);

    const uint4* src = (const uint4*)g_fN[buf];
    uint4 va[4], vb[4];
    load4(src, xA, yA, c8, va);
    load4(src, xB, yB, c8, vb);

    float accA[8] = {0}, accB[8] = {0};
    accum(va, fxA, fyA, accA);
    accum(vb, fxB, fyB, accB);

    store_h8(g_first, pA, c8, accA);
    store_h8(g_first, pB, c8, accB);
}

// ---------------------------------------------------------------------------
// Pass2 block: 64 pixels x 64 channels, 256 threads; smem-staged fp32 NCHW out.
// ---------------------------------------------------------------------------
__device__ __forceinline__ void pass2_block(const float* __restrict__ grid,
                                            float* __restrict__ out,
                                            int n, int blk,
                                            float* __restrict__ smf /*64*65*/) {
    const int t  = threadIdx.x;
    const int c8 = t & 7;
    const int px = t >> 3;
    const int p0 = blk * 64;
    const int pA = p0 + px;
    const int pB = pA + 32;

    const float2 gA = ((const float2*)grid)[(size_t)n * PP + pA];
    const float2 gB = ((const float2*)grid)[(size_t)n * PP + pB];
    int xA, yA, xB, yB; float fxA, fyA, fxB, fyB;
    bl_setup(gA.x, gA.y, xA, yA, fxA, fyA);
    bl_setup(gB.x, gB.y, xB, yB, fxB, fyB);

    const uint4* src = (const uint4*)g_first;
    uint4 va[4], vb[4];
    load4(src, xA, yA, c8, va);
    load4(src, xB, yB, c8, vb);

    float accA[8] = {0}, accB[8] = {0};
    accum(va, fxA, fyA, accA);
    accum(vb, fxB, fyB, accB);

    #pragma unroll
    for (int k = 0; k < 8; k++) {
        smf[(c8 * 8 + k) * 65 + px]      = accA[k];
        smf[(c8 * 8 + k) * 65 + px + 32] = accB[k];
    }
    __syncthreads();

    const int w = t >> 5, lane = t & 31;     // 8 warps x 8 channels each
    #pragma unroll
    for (int k = 0; k < 8; k++) {
        const int cc = w * 8 + k;
        const size_t ob = (((size_t)n * CH + cc) << 16) + p0;
        out[ob + lane]      = smf[cc * 65 + lane];
        out[ob + 32 + lane] = smf[cc * 65 + 32 + lane];
    }
    __syncthreads();
}

// ---------------------------------------------------------------------------
// Prologue: full transpose of batch 0 (1024 tiles).
// ---------------------------------------------------------------------------
__global__ void k_transpose0(const float* __restrict__ feat) {
    __shared__ float sm[64 * 65];
    transpose_tile(feat, 0, 0, blockIdx.x, sm);
}

// Fused A(n): blocks [0,512) transpose tiles 0..511 of batch n+1;
//             blocks [512,1536) = pass1(n).
__global__ void __launch_bounds__(256, 4)
k_fusedA(const float* __restrict__ feat, const float* __restrict__ grid, int n) {
    __shared__ float sm[64 * 65];
    if (blockIdx.x < 512) {
        if (n + 1 < NB)
            transpose_tile(feat, n + 1, (n + 1) & 1, blockIdx.x, sm);
    } else {
        pass1_block(grid, n, n & 1, blockIdx.x - 512);
    }
}

// Fused B(n): blocks [0,512) transpose tiles 512..1023 of batch n+1;
//             blocks [512,1536) = pass2(n).
__global__ void __launch_bounds__(256, 4)
k_fusedB(const float* __restrict__ feat, const float* __restrict__ grid,
         float* __restrict__ out, int n) {
    __shared__ float sm[64 * 65];
    if (blockIdx.x < 512) {
        if (n + 1 < NB)
            transpose_tile(feat, n + 1, (n + 1) & 1, 512 + blockIdx.x, sm);
    } else {
        pass2_block(grid, out, n, blockIdx.x - 512, sm);
    }
}

// ---------------------------------------------------------------------------
extern "C" void kernel_launch(void* const* d_in, const int* in_sizes, int n_in,
                              void* d_out, int out_size) {
    const float* feature = (const float*)d_in[0];
    const float* grid    = (const float*)d_in[1];
    float*       out     = (float*)d_out;

    k_transpose0<<<PP / 64, 256>>>(feature);
    for (int n = 0; n < NB; n++) {
        k_fusedA<<<512 + PP / 64, 256>>>(feature, grid, n);
        k_fusedB<<<512 + PP / 64, 256>>>(feature, grid, out, n);
    }
}

// round 7
// speedup vs baseline: 2.3358x; 1.1549x over previous
#include <cuda_runtime.h>
#include <cuda_fp16.h>

#define NB 8
#define CH 64
#define HH 256
#define WW 256
#define PP (HH*WW)   // 65536 pixels per batch

// fp16 scratch: 4-deep NHWC feature ring (4x8MB) + 2-deep NHWC intermediate
// (2x8MB). 48MB total -> L2-resident (126MB L2).
__device__ __half g_fN[4][(size_t)PP * CH];
__device__ __half g_first[2][(size_t)PP * CH];

// ---------------------------------------------------------------------------
// Transpose one 64ch x 64px tile of batch n: fp32 NCHW -> fp16 NHWC.
// ---------------------------------------------------------------------------
__device__ __forceinline__ void transpose_tile(const float* __restrict__ feat,
                                               int n, int tile,
                                               float* __restrict__ sm /*64*65*/) {
    const int pbase = tile * 64;
    const int t = threadIdx.x;
    const float* src = feat + (size_t)n * CH * PP;

    const int px4 = (t & 15) * 4;   // pixel offset 0..60
    const int c0  = t >> 4;         // 0..15
    #pragma unroll
    for (int i = 0; i < 4; i++) {
        const int c = c0 + i * 16;
        const float4 v = *(const float4*)(src + (size_t)c * PP + pbase + px4);
        sm[c * 65 + px4 + 0] = v.x;
        sm[c * 65 + px4 + 1] = v.y;
        sm[c * 65 + px4 + 2] = v.z;
        sm[c * 65 + px4 + 3] = v.w;
    }
    __syncthreads();

    __half* dst = g_fN[n & 3];
    const int c8  = t & 7;          // 8-channel chunk
    const int px0 = t >> 3;         // 0..31
    #pragma unroll
    for (int i = 0; i < 2; i++) {
        const int px = px0 + 32 * i;
        __half2 h[4];
        #pragma unroll
        for (int k = 0; k < 4; k++) {
            float2 f = make_float2(sm[(c8 * 8 + 2 * k) * 65 + px],
                                   sm[(c8 * 8 + 2 * k + 1) * 65 + px]);
            h[k] = __float22half2_rn(f);
        }
        ((uint4*)(dst + (size_t)(pbase + px) * 64))[c8] = *(uint4*)h;
    }
}

// ---------------------------------------------------------------------------
// Bilinear helpers (fp32 math, zeros padding; fp16 storage)
// ---------------------------------------------------------------------------
__device__ __forceinline__ void bl_setup(float gx, float gy,
                                         int& x0, int& y0, float& fx, float& fy) {
    float ix = ((gx + 1.0f) * (float)WW - 1.0f) * 0.5f;
    float iy = ((gy + 1.0f) * (float)HH - 1.0f) * 0.5f;
    float fx0 = floorf(ix);
    float fy0 = floorf(iy);
    fx = ix - fx0;
    fy = iy - fy0;
    x0 = (int)fx0;
    y0 = (int)fy0;
}

// Load the 4 corner uint4s (8 fp16 channels each) for one pixel.
__device__ __forceinline__ void load4(const uint4* __restrict__ src,
                                      int x0, int y0, int c8, uint4* v) {
    const int x1 = x0 + 1, y1 = y0 + 1;
    const bool vx0 = (x0 >= 0) & (x0 < WW);
    const bool vx1 = (x1 >= 0) & (x1 < WW);
    const bool vy0 = (y0 >= 0) & (y0 < HH);
    const bool vy1 = (y1 >= 0) & (y1 < HH);
    const uint4 z = make_uint4(0, 0, 0, 0);
    v[0] = (vx0 & vy0) ? src[(((y0 << 8) + x0) << 3) + c8] : z;
    v[1] = (vx1 & vy0) ? src[(((y0 << 8) + x1) << 3) + c8] : z;
    v[2] = (vx0 & vy1) ? src[(((y1 << 8) + x0) << 3) + c8] : z;
    v[3] = (vx1 & vy1) ? src[(((y1 << 8) + x1) << 3) + c8] : z;
}

// Weighted accumulate of 4 corner uint4s into 8 fp32 channel values.
__device__ __forceinline__ void accum(const uint4* v, float fx, float fy,
                                      float* acc) {
    const float wx1 = fx, wy1 = fy, wx0 = 1.0f - fx, wy0 = 1.0f - fy;
    const float w[4] = {wx0 * wy0, wx1 * wy0, wx0 * wy1, wx1 * wy1};
    #pragma unroll
    for (int j = 0; j < 4; j++) {
        const __half2* h = (const __half2*)&v[j];
        #pragma unroll
        for (int k = 0; k < 4; k++) {
            float2 f = __half22float2(h[k]);
            acc[2 * k]     += f.x * w[j];
            acc[2 * k + 1] += f.y * w[j];
        }
    }
}

__device__ __forceinline__ void store_h8(__half* __restrict__ dst, int p, int c8,
                                         const float* acc) {
    __half2 h[4];
    #pragma unroll
    for (int k = 0; k < 4; k++)
        h[k] = __float22half2_rn(make_float2(acc[2 * k], acc[2 * k + 1]));
    ((uint4*)(dst + (size_t)p * 64))[c8] = *(uint4*)h;
}

// ---------------------------------------------------------------------------
// Pass1 block: 64 pixels x 64 channels, 256 threads, 2 pixels/thread.
// ---------------------------------------------------------------------------
__device__ __forceinline__ void pass1_block(const float* __restrict__ grid,
                                            int n, int blk) {
    const int t  = threadIdx.x;
    const int c8 = t & 7;
    const int px = t >> 3;
    const int pA = blk * 64 + px;
    const int pB = pA + 32;

    const float2 gA = ((const float2*)grid)[(size_t)n * PP + pA];
    const float2 gB = ((const float2*)grid)[(size_t)n * PP + pB];
    int xA, yA, xB, yB; float fxA, fyA, fxB, fyB;
    bl_setup(gA.x, gA.y, xA, yA, fxA, fyA);
    bl_setup(gB.x, gB.y, xB, yB, fxB, fyB);

    const uint4* src = (const uint4*)g_fN[n & 3];
    uint4 va[4], vb[4];
    load4(src, xA, yA, c8, va);
    load4(src, xB, yB, c8, vb);

    float accA[8] = {0}, accB[8] = {0};
    accum(va, fxA, fyA, accA);
    accum(vb, fxB, fyB, accB);

    __half* dst = g_first[n & 1];
    store_h8(dst, pA, c8, accA);
    store_h8(dst, pB, c8, accB);
}

// ---------------------------------------------------------------------------
// Pass2 block: 64 pixels x 64 channels, 256 threads; smem-staged fp32 NCHW out.
// ---------------------------------------------------------------------------
__device__ __forceinline__ void pass2_block(const float* __restrict__ grid,
                                            float* __restrict__ out,
                                            int n, int blk,
                                            float* __restrict__ smf /*64*65*/) {
    const int t  = threadIdx.x;
    const int c8 = t & 7;
    const int px = t >> 3;
    const int p0 = blk * 64;
    const int pA = p0 + px;
    const int pB = pA + 32;

    const float2 gA = ((const float2*)grid)[(size_t)n * PP + pA];
    const float2 gB = ((const float2*)grid)[(size_t)n * PP + pB];
    int xA, yA, xB, yB; float fxA, fyA, fxB, fyB;
    bl_setup(gA.x, gA.y, xA, yA, fxA, fyA);
    bl_setup(gB.x, gB.y, xB, yB, fxB, fyB);

    const uint4* src = (const uint4*)g_first[n & 1];
    uint4 va[4], vb[4];
    load4(src, xA, yA, c8, va);
    load4(src, xB, yB, c8, vb);

    float accA[8] = {0}, accB[8] = {0};
    accum(va, fxA, fyA, accA);
    accum(vb, fxB, fyB, accB);

    #pragma unroll
    for (int k = 0; k < 8; k++) {
        smf[(c8 * 8 + k) * 65 + px]      = accA[k];
        smf[(c8 * 8 + k) * 65 + px + 32] = accB[k];
    }
    __syncthreads();

    const int w = t >> 5, lane = t & 31;     // 8 warps x 8 channels each
    #pragma unroll
    for (int k = 0; k < 8; k++) {
        const int cc = w * 8 + k;
        const size_t ob = (((size_t)n * CH + cc) << 16) + p0;
        out[ob + lane]      = smf[cc * 65 + lane];
        out[ob + 32 + lane] = smf[cc * 65 + 32 + lane];
    }
}

// ---------------------------------------------------------------------------
// Prologue: transpose batches 0 and 1 (2048 tiles).
// ---------------------------------------------------------------------------
__global__ void __launch_bounds__(256, 5)
k_transpose01(const float* __restrict__ feat) {
    __shared__ float sm[64 * 65];
    transpose_tile(feat, blockIdx.x >> 10, blockIdx.x & 1023, sm);
}

// Fused A(m): blocks [0,1024) = transpose batch m+2 (if exists);
//             blocks [1024, 3072) = pass1 for batches m and m+1.
__global__ void __launch_bounds__(256, 5)
k_fusedA(const float* __restrict__ feat, const float* __restrict__ grid, int m) {
    __shared__ float sm[64 * 65];
    if (blockIdx.x < 1024) {
        if (m + 2 < NB)
            transpose_tile(feat, m + 2, blockIdx.x, sm);
    } else {
        const int b = blockIdx.x - 1024;
        pass1_block(grid, m + (b >> 10), b & 1023);
    }
}

// Fused B(m): blocks [0,1024) = transpose batch m+3 (if exists);
//             blocks [1024, 3072) = pass2 for batches m and m+1.
__global__ void __launch_bounds__(256, 5)
k_fusedB(const float* __restrict__ feat, const float* __restrict__ grid,
         float* __restrict__ out, int m) {
    __shared__ float sm[64 * 65];
    if (blockIdx.x < 1024) {
        if (m + 3 < NB)
            transpose_tile(feat, m + 3, blockIdx.x, sm);
    } else {
        const int b = blockIdx.x - 1024;
        pass2_block(grid, out, m + (b >> 10), b & 1023, sm);
    }
}

// ---------------------------------------------------------------------------
extern "C" void kernel_launch(void* const* d_in, const int* in_sizes, int n_in,
                              void* d_out, int out_size) {
    const float* feature = (const float*)d_in[0];
    const float* grid    = (const float*)d_in[1];
    float*       out     = (float*)d_out;

    k_transpose01<<<2048, 256>>>(feature);
    for (int m = 0; m < NB; m += 2) {
        k_fusedA<<<3072, 256>>>(feature, grid, m);
        k_fusedB<<<3072, 256>>>(feature, grid, out, m);
    }
}

// round 8
// speedup vs baseline: 2.7692x; 1.1855x over previous
#include <cuda_runtime.h>
#include <cuda_fp16.h>

#define NB 8
#define CH 64
#define HH 256
#define WW 256
#define PP (HH*WW)   // 65536 pixels per batch

// fp16 scratch: 8-deep NHWC feature ring (8x8MB=64MB) + 2-deep NHWC
// intermediate (2x8MB). Hot working set ~40MB -> L2-resident (126MB L2).
// 8-deep ring makes the sync-free transpose blocks race-free under PDL
// overlap (only adjacent launches can be concurrent; all buffers touched by
// concurrent grids are disjoint).
__device__ __half g_fN[8][(size_t)PP * CH];
__device__ __half g_first[2][(size_t)PP * CH];

// ---------------------------------------------------------------------------
// Transpose one 64ch x 64px tile of batch n: fp32 NCHW -> fp16 NHWC.
// ---------------------------------------------------------------------------
__device__ __forceinline__ void transpose_tile(const float* __restrict__ feat,
                                               int n, int tile,
                                               float* __restrict__ sm /*64*65*/) {
    const int pbase = tile * 64;
    const int t = threadIdx.x;
    const float* src = feat + (size_t)n * CH * PP;

    const int px4 = (t & 15) * 4;   // pixel offset 0..60
    const int c0  = t >> 4;         // 0..15
    #pragma unroll
    for (int i = 0; i < 4; i++) {
        const int c = c0 + i * 16;
        const float4 v = *(const float4*)(src + (size_t)c * PP + pbase + px4);
        sm[c * 65 + px4 + 0] = v.x;
        sm[c * 65 + px4 + 1] = v.y;
        sm[c * 65 + px4 + 2] = v.z;
        sm[c * 65 + px4 + 3] = v.w;
    }
    __syncthreads();

    __half* dst = g_fN[n & 7];
    const int c8  = t & 7;          // 8-channel chunk
    const int px0 = t >> 3;         // 0..31
    #pragma unroll
    for (int i = 0; i < 2; i++) {
        const int px = px0 + 32 * i;
        __half2 h[4];
        #pragma unroll
        for (int k = 0; k < 4; k++) {
            float2 f = make_float2(sm[(c8 * 8 + 2 * k) * 65 + px],
                                   sm[(c8 * 8 + 2 * k + 1) * 65 + px]);
            h[k] = __float22half2_rn(f);
        }
        ((uint4*)(dst + (size_t)(pbase + px) * 64))[c8] = *(uint4*)h;
    }
}

// ---------------------------------------------------------------------------
// Bilinear helpers (fp32 math, zeros padding; fp16 storage)
// ---------------------------------------------------------------------------
__device__ __forceinline__ void bl_setup(float gx, float gy,
                                         int& x0, int& y0, float& fx, float& fy) {
    float ix = ((gx + 1.0f) * (float)WW - 1.0f) * 0.5f;
    float iy = ((gy + 1.0f) * (float)HH - 1.0f) * 0.5f;
    float fx0 = floorf(ix);
    float fy0 = floorf(iy);
    fx = ix - fx0;
    fy = iy - fy0;
    x0 = (int)fx0;
    y0 = (int)fy0;
}

// Load the 4 corner uint4s (8 fp16 channels each) for one pixel.
__device__ __forceinline__ void load4(const uint4* __restrict__ src,
                                      int x0, int y0, int c8, uint4* v) {
    const int x1 = x0 + 1, y1 = y0 + 1;
    const bool vx0 = (x0 >= 0) & (x0 < WW);
    const bool vx1 = (x1 >= 0) & (x1 < WW);
    const bool vy0 = (y0 >= 0) & (y0 < HH);
    const bool vy1 = (y1 >= 0) & (y1 < HH);
    const uint4 z = make_uint4(0, 0, 0, 0);
    v[0] = (vx0 & vy0) ? src[(((y0 << 8) + x0) << 3) + c8] : z;
    v[1] = (vx1 & vy0) ? src[(((y0 << 8) + x1) << 3) + c8] : z;
    v[2] = (vx0 & vy1) ? src[(((y1 << 8) + x0) << 3) + c8] : z;
    v[3] = (vx1 & vy1) ? src[(((y1 << 8) + x1) << 3) + c8] : z;
}

// Weighted accumulate of 4 corner uint4s into 8 fp32 channel values.
__device__ __forceinline__ void accum(const uint4* v, float fx, float fy,
                                      float* acc) {
    const float wx1 = fx, wy1 = fy, wx0 = 1.0f - fx, wy0 = 1.0f - fy;
    const float w[4] = {wx0 * wy0, wx1 * wy0, wx0 * wy1, wx1 * wy1};
    #pragma unroll
    for (int j = 0; j < 4; j++) {
        const __half2* h = (const __half2*)&v[j];
        #pragma unroll
        for (int k = 0; k < 4; k++) {
            float2 f = __half22float2(h[k]);
            acc[2 * k]     += f.x * w[j];
            acc[2 * k + 1] += f.y * w[j];
        }
    }
}

__device__ __forceinline__ void store_h8(__half* __restrict__ dst, int p, int c8,
                                         const float* acc) {
    __half2 h[4];
    #pragma unroll
    for (int k = 0; k < 4; k++)
        h[k] = __float22half2_rn(make_float2(acc[2 * k], acc[2 * k + 1]));
    ((uint4*)(dst + (size_t)p * 64))[c8] = *(uint4*)h;
}

// ---------------------------------------------------------------------------
// Pass1 block: 64 pixels x 64 channels, 256 threads, 2 pixels/thread.
// ---------------------------------------------------------------------------
__device__ __forceinline__ void pass1_block(const float* __restrict__ grid,
                                            int n, int blk) {
    const int t  = threadIdx.x;
    const int c8 = t & 7;
    const int px = t >> 3;
    const int pA = blk * 64 + px;
    const int pB = pA + 32;

    const float2 gA = ((const float2*)grid)[(size_t)n * PP + pA];
    const float2 gB = ((const float2*)grid)[(size_t)n * PP + pB];
    int xA, yA, xB, yB; float fxA, fyA, fxB, fyB;
    bl_setup(gA.x, gA.y, xA, yA, fxA, fyA);
    bl_setup(gB.x, gB.y, xB, yB, fxB, fyB);

    const uint4* src = (const uint4*)g_fN[n & 7];
    uint4 va[4], vb[4];
    load4(src, xA, yA, c8, va);
    load4(src, xB, yB, c8, vb);

    float accA[8] = {0}, accB[8] = {0};
    accum(va, fxA, fyA, accA);
    accum(vb, fxB, fyB, accB);

    __half* dst = g_first[n & 1];
    store_h8(dst, pA, c8, accA);
    store_h8(dst, pB, c8, accB);
}

// ---------------------------------------------------------------------------
// Pass2 block: 64 pixels x 64 channels, 256 threads; smem-staged fp32 NCHW out.
// ---------------------------------------------------------------------------
__device__ __forceinline__ void pass2_block(const float* __restrict__ grid,
                                            float* __restrict__ out,
                                            int n, int blk,
                                            float* __restrict__ smf /*64*65*/) {
    const int t  = threadIdx.x;
    const int c8 = t & 7;
    const int px = t >> 3;
    const int p0 = blk * 64;
    const int pA = p0 + px;
    const int pB = pA + 32;

    const float2 gA = ((const float2*)grid)[(size_t)n * PP + pA];
    const float2 gB = ((const float2*)grid)[(size_t)n * PP + pB];
    int xA, yA, xB, yB; float fxA, fyA, fxB, fyB;
    bl_setup(gA.x, gA.y, xA, yA, fxA, fyA);
    bl_setup(gB.x, gB.y, xB, yB, fxB, fyB);

    const uint4* src = (const uint4*)g_first[n & 1];
    uint4 va[4], vb[4];
    load4(src, xA, yA, c8, va);
    load4(src, xB, yB, c8, vb);

    float accA[8] = {0}, accB[8] = {0};
    accum(va, fxA, fyA, accA);
    accum(vb, fxB, fyB, accB);

    #pragma unroll
    for (int k = 0; k < 8; k++) {
        smf[(c8 * 8 + k) * 65 + px]      = accA[k];
        smf[(c8 * 8 + k) * 65 + px + 32] = accB[k];
    }
    __syncthreads();

    const int w = t >> 5, lane = t & 31;     // 8 warps x 8 channels each
    #pragma unroll
    for (int k = 0; k < 8; k++) {
        const int cc = w * 8 + k;
        const size_t ob = (((size_t)n * CH + cc) << 16) + p0;
        out[ob + lane]      = smf[cc * 65 + lane];
        out[ob + 32 + lane] = smf[cc * 65 + 32 + lane];
    }
}

// ---------------------------------------------------------------------------
// Prologue: transpose batches 0 and 1 (2048 tiles). Launched without PDL.
// ---------------------------------------------------------------------------
__global__ void __launch_bounds__(256, 5)
k_transpose01(const float* __restrict__ feat) {
    cudaTriggerProgrammaticLaunchCompletion();
    __shared__ float sm[64 * 65];
    transpose_tile(feat, blockIdx.x >> 10, blockIdx.x & 1023, sm);
}

// Fused A(m): blocks [0,1024) = transpose batch m+2 (sync-free tail filler);
//             blocks [1024, 3072) = pass1 for batches m and m+1 (synced).
__global__ void __launch_bounds__(256, 5)
k_fusedA(const float* __restrict__ feat, const float* __restrict__ grid, int m) {
    cudaTriggerProgrammaticLaunchCompletion();
    __shared__ float sm[64 * 65];
    if (blockIdx.x < 1024) {
        if (m + 2 < NB)
            transpose_tile(feat, m + 2, blockIdx.x, sm);
    } else {
        cudaGridDependencySynchronize();   // wait predecessor (prologue / B(m-2))
        const int b = blockIdx.x - 1024;
        pass1_block(grid, m + (b >> 10), b & 1023);
    }
}

// Fused B(m): blocks [0,1024) = transpose batch m+3 (sync-free tail filler);
//             blocks [1024, 3072) = pass2 for batches m and m+1 (synced).
__global__ void __launch_bounds__(256, 5)
k_fusedB(const float* __restrict__ feat, const float* __restrict__ grid,
         float* __restrict__ out, int m) {
    cudaTriggerProgrammaticLaunchCompletion();
    __shared__ float sm[64 * 65];
    if (blockIdx.x < 1024) {
        if (m + 3 < NB)
            transpose_tile(feat, m + 3, blockIdx.x, sm);
    } else {
        cudaGridDependencySynchronize();   // wait A(m) (pass1 results)
        const int b = blockIdx.x - 1024;
        pass2_block(grid, out, m + (b >> 10), b & 1023, sm);
    }
}

// ---------------------------------------------------------------------------
static inline void launch_pdl(void* func, dim3 grid, void** args) {
    cudaLaunchConfig_t cfg = {};
    cfg.gridDim = grid;
    cfg.blockDim = dim3(256, 1, 1);
    cfg.dynamicSmemBytes = 0;
    cfg.stream = 0;
    cudaLaunchAttribute attr[1];
    attr[0].id = cudaLaunchAttributeProgrammaticStreamSerialization;
    attr[0].val.programmaticStreamSerializationAllowed = 1;
    cfg.attrs = attr;
    cfg.numAttrs = 1;
    cudaLaunchKernelExC(&cfg, func, args);
}

extern "C" void kernel_launch(void* const* d_in, const int* in_sizes, int n_in,
                              void* d_out, int out_size) {
    const float* feature = (const float*)d_in[0];
    const float* grid    = (const float*)d_in[1];
    float*       out     = (float*)d_out;

    k_transpose01<<<2048, 256>>>(feature);
    for (int m = 0; m < NB; m += 2) {
        {
            void* args[] = {(void*)&feature, (void*)&grid, (void*)&m};
            launch_pdl((void*)k_fusedA, dim3(3072), args);
        }
        {
            void* args[] = {(void*)&feature, (void*)&grid, (void*)&out, (void*)&m};
            launch_pdl((void*)k_fusedB, dim3(3072), args);
        }
    }
}